// round 8
// baseline (speedup 1.0000x reference)
#include <cuda_runtime.h>
#include <cuda_bf16.h>
#include <cstdint>

// ---------------- problem constants ----------------
#define NWIN   2048
#define NTOK   66
#define MTOT   (NWIN * NTOK)       // 135168
#define DIM    256
#define QKVN   768
#define NHEAD  8
#define HD     32
#define TOKNUM 2
#define GK     256

// ---------------- scratch ----------------
__device__ float          g_qkv [(size_t)MTOT * QKVN];
__device__ __nv_bfloat16  g_xhi [(size_t)MTOT * DIM];
__device__ __nv_bfloat16  g_xlo [(size_t)MTOT * DIM];
__device__ __nv_bfloat16  g_ahi [(size_t)MTOT * DIM];
__device__ __nv_bfloat16  g_alo [(size_t)MTOT * DIM];
__device__ __nv_bfloat16  g_qwhi[(size_t)QKVN * DIM];
__device__ __nv_bfloat16  g_qwlo[(size_t)QKVN * DIM];
__device__ __nv_bfloat16  g_pwhi[(size_t)DIM * DIM];
__device__ __nv_bfloat16  g_pwlo[(size_t)DIM * DIM];

// ---------------- helpers ----------------
__device__ __forceinline__ uint32_t smem_u32(const void* p) {
    uint32_t a;
    asm("{ .reg .u64 t; cvta.to.shared.u64 t, %1; cvt.u32.u64 %0, t; }"
        : "=r"(a) : "l"(p));
    return a;
}
__device__ __forceinline__ void ldsm4(uint32_t* r, uint32_t addr) {
    asm volatile("ldmatrix.sync.aligned.m8n8.x4.shared.b16 {%0,%1,%2,%3}, [%4];"
                 : "=r"(r[0]), "=r"(r[1]), "=r"(r[2]), "=r"(r[3]) : "r"(addr));
}
__device__ __forceinline__ void mma_bf16(float* c, const uint32_t* a,
                                         uint32_t b0, uint32_t b1) {
    asm volatile("mma.sync.aligned.m16n8k16.row.col.f32.bf16.bf16.f32 "
                 "{%0,%1,%2,%3}, {%4,%5,%6,%7}, {%8,%9}, {%0,%1,%2,%3};"
                 : "+f"(c[0]), "+f"(c[1]), "+f"(c[2]), "+f"(c[3])
                 : "r"(a[0]), "r"(a[1]), "r"(a[2]), "r"(a[3]),
                   "r"(b0), "r"(b1));
}
#define CP_ASYNC16(dst, src) \
    asm volatile("cp.async.cg.shared.global [%0], [%1], 16;" :: "r"(dst), "l"(src))
#define CP_COMMIT() asm volatile("cp.async.commit_group;" ::: "memory")

// ---------------- fp32 -> bf16 hi/lo split ----------------
__global__ void split_kernel(const float* __restrict__ in,
                             __nv_bfloat16* __restrict__ hi,
                             __nv_bfloat16* __restrict__ lo, int n4)
{
    int i = blockIdx.x * blockDim.x + threadIdx.x;
    if (i >= n4) return;
    float4 v = ((const float4*)in)[i];
    __nv_bfloat16 h0 = __float2bfloat16(v.x);
    __nv_bfloat16 h1 = __float2bfloat16(v.y);
    __nv_bfloat16 h2 = __float2bfloat16(v.z);
    __nv_bfloat16 h3 = __float2bfloat16(v.w);
    __nv_bfloat16 l0 = __float2bfloat16(v.x - __bfloat162float(h0));
    __nv_bfloat16 l1 = __float2bfloat16(v.y - __bfloat162float(h1));
    __nv_bfloat16 l2 = __float2bfloat16(v.z - __bfloat162float(h2));
    __nv_bfloat16 l3 = __float2bfloat16(v.w - __bfloat162float(h3));
    ((__nv_bfloat162*)hi)[2 * i + 0] = __nv_bfloat162(h0, h1);
    ((__nv_bfloat162*)hi)[2 * i + 1] = __nv_bfloat162(h2, h3);
    ((__nv_bfloat162*)lo)[2 * i + 0] = __nv_bfloat162(l0, l1);
    ((__nv_bfloat162*)lo)[2 * i + 1] = __nv_bfloat162(l2, l3);
}

// ---------------- HMMA GEMM: BK=32, 4 stages, 1 sync/chunk ----------------
#define BM 128
#define BN 128
#define BKK 32
#define KSTRIDE 40                       // padded bf16 row stride (80B)
#define ARR_ELEMS (128 * KSTRIDE)        // 5120 bf16 per array
#define STAGE_ELEMS (4 * ARR_ELEMS)      // Ahi|Alo|Bhi|Blo = 20480 bf16
#define STAGES 4
#define GEMM_SMEM (STAGES * STAGE_ELEMS * 2)   // 163840 bytes
#define NCHUNK (GK / BKK)                // 8

__global__ __launch_bounds__(256)
void gemm_mma_kernel(const __nv_bfloat16* __restrict__ Ahi,
                     const __nv_bfloat16* __restrict__ Alo,
                     const __nv_bfloat16* __restrict__ Bhi,
                     const __nv_bfloat16* __restrict__ Blo,
                     const float* __restrict__ bias,
                     float* __restrict__ C, int N)
{
    extern __shared__ __nv_bfloat16 smbuf[];
    const uint32_t sbase = smem_u32(smbuf);
    const int tid  = threadIdx.x;
    const int lane = tid & 31;
    const int wid  = tid >> 5;
    const int wm   = wid >> 2;
    const int wn   = wid & 3;
    const int m0 = blockIdx.x * BM;
    const int n0 = blockIdx.y * BN;

    float acc[4][4][4];
#pragma unroll
    for (int i = 0; i < 4; i++)
#pragma unroll
        for (int j = 0; j < 4; j++)
#pragma unroll
            for (int q = 0; q < 4; q++) acc[i][j][q] = 0.0f;

    auto load_stage = [&](int c, int s) {
        const int k0 = c * BKK;
#pragma unroll
        for (int it = 0; it < 8; it++) {
            int t = tid + it * 256;
            int arr = t >> 9;
            int rem = t & 511;
            int row = rem >> 2;
            int ch  = rem & 3;
            const __nv_bfloat16* g;
            if (arr == 0)      g = Ahi + (size_t)(m0 + row) * GK + k0 + ch * 8;
            else if (arr == 1) g = Alo + (size_t)(m0 + row) * GK + k0 + ch * 8;
            else if (arr == 2) g = Bhi + (size_t)(n0 + row) * GK + k0 + ch * 8;
            else               g = Blo + (size_t)(n0 + row) * GK + k0 + ch * 8;
            uint32_t dst = sbase +
                (uint32_t)(s * STAGE_ELEMS + arr * ARR_ELEMS + row * KSTRIDE + ch * 8) * 2u;
            CP_ASYNC16(dst, g);
        }
        CP_COMMIT();
    };

    load_stage(0, 0);
    load_stage(1, 1);
    load_stage(2, 2);

    const int a_row = (lane & 15);
    const int a_kof = (lane >> 4) << 3;
    const int b_row = (lane & 7) + ((lane >> 4) << 3);
    const int b_kof = ((lane >> 3) & 1) << 3;

    for (int c = 0; c < NCHUNK; c++) {
        if (c < NCHUNK - 2)       asm volatile("cp.async.wait_group 2;" ::: "memory");
        else if (c == NCHUNK - 2) asm volatile("cp.async.wait_group 1;" ::: "memory");
        else                      asm volatile("cp.async.wait_group 0;" ::: "memory");
        __syncthreads();
        // prefetch distance 3: targets buffer (c-1)&3, fully consumed last chunk
        if (c + 3 < NCHUNK) load_stage(c + 3, (c + 3) & (STAGES - 1));

        const uint32_t st = sbase + (uint32_t)((c & (STAGES - 1)) * STAGE_ELEMS) * 2u;
        const uint32_t sAhi = st;
        const uint32_t sAlo = st + ARR_ELEMS * 2u;
        const uint32_t sBhi = st + 2u * ARR_ELEMS * 2u;
        const uint32_t sBlo = st + 3u * ARR_ELEMS * 2u;

#pragma unroll
        for (int ks = 0; ks < 2; ks++) {
            uint32_t ah[4][4], al[4][4], bh[2][4], bl[2][4];
#pragma unroll
            for (int mi = 0; mi < 4; mi++) {
                int row = wm * 64 + mi * 16 + a_row;
                int k   = ks * 16 + a_kof;
                uint32_t off = (uint32_t)(row * KSTRIDE + k) * 2u;
                ldsm4(ah[mi], sAhi + off);
                ldsm4(al[mi], sAlo + off);
            }
#pragma unroll
            for (int nt = 0; nt < 2; nt++) {
                int row = wn * 32 + nt * 16 + b_row;
                int k   = ks * 16 + b_kof;
                uint32_t off = (uint32_t)(row * KSTRIDE + k) * 2u;
                ldsm4(bh[nt], sBhi + off);
                ldsm4(bl[nt], sBlo + off);
            }
#pragma unroll
            for (int mi = 0; mi < 4; mi++)
#pragma unroll
                for (int nj = 0; nj < 4; nj++) {
                    uint32_t h0 = bh[nj >> 1][(nj & 1) * 2];
                    uint32_t h1 = bh[nj >> 1][(nj & 1) * 2 + 1];
                    uint32_t l0 = bl[nj >> 1][(nj & 1) * 2];
                    uint32_t l1 = bl[nj >> 1][(nj & 1) * 2 + 1];
                    mma_bf16(acc[mi][nj], ah[mi], h0, h1);
                    mma_bf16(acc[mi][nj], ah[mi], l0, l1);
                    mma_bf16(acc[mi][nj], al[mi], h0, h1);
                }
        }
    }

#pragma unroll
    for (int mi = 0; mi < 4; mi++) {
        int row = m0 + wm * 64 + mi * 16 + (lane >> 2);
#pragma unroll
        for (int nj = 0; nj < 4; nj++) {
            int col = n0 + wn * 32 + nj * 8 + (lane & 3) * 2;
            float2 bv = *(const float2*)&bias[col];
            float2 v0 = make_float2(acc[mi][nj][0] + bv.x, acc[mi][nj][1] + bv.y);
            float2 v1 = make_float2(acc[mi][nj][2] + bv.x, acc[mi][nj][3] + bv.y);
            *(float2*)&C[(size_t)row * N + col] = v0;
            *(float2*)&C[(size_t)(row + 8) * N + col] = v1;
        }
    }
}

// ---------------- attention: 4 heads per CTA, 2 CTAs per window ------------
#define HB       4                         // heads per CTA
#define ATT_THREADS 288                    // 9 warps; 264 workers
#define AOFF_VSM  (HB * 66 * 32)           // 8448 floats
#define AOFF_OHI  (2 * HB * 66 * 32)       // 16896
#define AOFF_OLO  (AOFF_OHI + (66 * 128) / 2)   // +4224
#define AOFF_TAB  (AOFF_OLO + (66 * 128) / 2)
#define ATT_SMEM  ((AOFF_TAB + 1800) * 4)  // 108576 bytes -> 2 CTAs/SM

__global__ __launch_bounds__(ATT_THREADS, 2)
void attn_kernel(const float* __restrict__ qkv,
                 const float* __restrict__ table,
                 __nv_bfloat16* __restrict__ ohi,
                 __nv_bfloat16* __restrict__ olo)
{
    extern __shared__ float sm[];
    float* ksm = sm;
    float* vsm = sm + AOFF_VSM;
    __nv_bfloat16* osm_hi = (__nv_bfloat16*)(sm + AOFF_OHI);
    __nv_bfloat16* osm_lo = (__nv_bfloat16*)(sm + AOFF_OLO);
    float* tab = sm + AOFF_TAB;

    const int b = blockIdx.x;
    const int hbase = blockIdx.y * HB;
    const int tid = threadIdx.x;
    const size_t base = (size_t)b * NTOK * QKVN;

    // load K/V for this CTA's 4 heads: 66 tokens x 64 float4 (32 K + 32 V)
    for (int t = tid; t < NTOK * 64; t += ATT_THREADS) {
        int tok = t >> 6;
        int r = t & 63;
        int isV = r >> 5;                  // 0:K 1:V
        int c4 = r & 31;                   // float4 index within 128 floats
        float4 v = *(const float4*)&qkv[base + (size_t)tok * QKVN + 256 +
                                        isV * 256 + hbase * 32 + c4 * 4];
        int lh = c4 >> 3, d = (c4 & 7) * 4;
        float* dstp = isV ? vsm : ksm;
        *(float4*)&dstp[(lh * NTOK + tok) * 32 + d] = v;
    }
    for (int t = tid; t < 1800; t += ATT_THREADS) tab[t] = table[t];
    __syncthreads();

    if (tid < HB * NTOK) {
        const int lh = tid / NTOK;
        const int i = tid - lh * NTOK;
        const int h = hbase + lh;
        const float scale = 0.1767766952966369f;

        float qr[32];
#pragma unroll
        for (int d4 = 0; d4 < 8; d4++) {
            float4 qv = *(const float4*)&qkv[base + (size_t)i * QKVN + h * 32 + d4 * 4];
            qr[d4 * 4 + 0] = qv.x * scale; qr[d4 * 4 + 1] = qv.y * scale;
            qr[d4 * 4 + 2] = qv.z * scale; qr[d4 * 4 + 3] = qv.w * scale;
        }

        const float* krow = &ksm[lh * NTOK * 32];
        const float* vrow = &vsm[lh * NTOK * 32];
        const bool addbias = (i >= TOKNUM);
        const int qi = addbias ? (i - TOKNUM) : 0;
        const int yi = qi >> 3, xi = qi & 7;

        auto score = [&](int j) -> float {
            float a0 = 0.f, a1 = 0.f, a2 = 0.f, a3 = 0.f;
            const float* kp = &krow[j * 32];
#pragma unroll
            for (int d4 = 0; d4 < 8; d4++) {
                float4 kv = *(const float4*)&kp[d4 * 4];
                a0 = fmaf(qr[d4 * 4 + 0], kv.x, a0);
                a1 = fmaf(qr[d4 * 4 + 1], kv.y, a1);
                a2 = fmaf(qr[d4 * 4 + 2], kv.z, a2);
                a3 = fmaf(qr[d4 * 4 + 3], kv.w, a3);
            }
            return (a0 + a1) + (a2 + a3);
        };

        float4 oacc[8];
        float s0 = score(0);
        float s1 = score(1);
        float m = fmaxf(s0, s1);
        float p0 = __expf(s0 - m);
        float p1 = __expf(s1 - m);
        float l = p0 + p1;
        {
            const float* v0 = &vrow[0];
            const float* v1 = &vrow[32];
#pragma unroll
            for (int d4 = 0; d4 < 8; d4++) {
                float4 va = *(const float4*)&v0[d4 * 4];
                float4 vb = *(const float4*)&v1[d4 * 4];
                oacc[d4].x = p0 * va.x + p1 * vb.x;
                oacc[d4].y = p0 * va.y + p1 * vb.y;
                oacc[d4].z = p0 * va.z + p1 * vb.z;
                oacc[d4].w = p0 * va.w + p1 * vb.w;
            }
        }

        for (int jb = 0; jb < 8; jb++) {
            const float* trow = &tab[(((yi - jb + 7) * 15) + xi + 7) * NHEAD + h];
            float sc[8];
            float bm = -1e30f;
#pragma unroll
            for (int jj = 0; jj < 8; jj++) {
                float s = score(jb * 8 + jj + TOKNUM);
                if (addbias) s += trow[-jj * NHEAD];
                sc[jj] = s;
                bm = fmaxf(bm, s);
            }
            float m_new = fmaxf(m, bm);
            float f = __expf(m - m_new);
            m = m_new;
            l *= f;
#pragma unroll
            for (int d4 = 0; d4 < 8; d4++) {
                oacc[d4].x *= f; oacc[d4].y *= f;
                oacc[d4].z *= f; oacc[d4].w *= f;
            }
#pragma unroll
            for (int jj = 0; jj < 8; jj++) {
                float p = __expf(sc[jj] - m);
                l += p;
                const float* vp = &vrow[(jb * 8 + jj + TOKNUM) * 32];
#pragma unroll
                for (int d4 = 0; d4 < 8; d4++) {
                    float4 vv = *(const float4*)&vp[d4 * 4];
                    oacc[d4].x = fmaf(p, vv.x, oacc[d4].x);
                    oacc[d4].y = fmaf(p, vv.y, oacc[d4].y);
                    oacc[d4].z = fmaf(p, vv.z, oacc[d4].z);
                    oacc[d4].w = fmaf(p, vv.w, oacc[d4].w);
                }
            }
        }

        const float inv = 1.0f / l;
        __nv_bfloat16* ph = &osm_hi[i * 128 + lh * 32];
        __nv_bfloat16* pl = &osm_lo[i * 128 + lh * 32];
#pragma unroll
        for (int d4 = 0; d4 < 8; d4++) {
            float o[4] = {oacc[d4].x * inv, oacc[d4].y * inv,
                          oacc[d4].z * inv, oacc[d4].w * inv};
#pragma unroll
            for (int q = 0; q < 4; q++) {
                __nv_bfloat16 hh = __float2bfloat16(o[q]);
                ph[d4 * 4 + q] = hh;
                pl[d4 * 4 + q] = __float2bfloat16(o[q] - __bfloat162float(hh));
            }
        }
    }
    __syncthreads();

    // flush: 66 rows x 128 bf16 at row stride 256, offset hbase*32 channels
    uint4* gh = (uint4*)(ohi + (size_t)b * NTOK * DIM + hbase * 32);
    uint4* gl = (uint4*)(olo + (size_t)b * NTOK * DIM + hbase * 32);
    const uint4* shh = (const uint4*)osm_hi;
    const uint4* sll = (const uint4*)osm_lo;
    for (int t = tid; t < NTOK * 16; t += ATT_THREADS) {
        int row = t >> 4;
        int c = t & 15;
        gh[row * 32 + c] = shh[t];
        gl[row * 32 + c] = sll[t];
    }
}

// ---------------------------------------------------------------------------
extern "C" void kernel_launch(void* const* d_in, const int* in_sizes, int n_in,
                              void* d_out, int out_size)
{
    const float* x      = (const float*)d_in[0];
    const float* qkv_w  = (const float*)d_in[1];
    const float* qkv_b  = (const float*)d_in[2];
    const float* table  = (const float*)d_in[3];
    const float* proj_w = (const float*)d_in[4];
    const float* proj_b = (const float*)d_in[5];
    float* out = (float*)d_out;

    __nv_bfloat16 *xhi, *xlo, *ahi, *alo, *qwhi, *qwlo, *pwhi, *pwlo;
    float* qkv_s;
    cudaGetSymbolAddress((void**)&qkv_s, g_qkv);
    cudaGetSymbolAddress((void**)&xhi,  g_xhi);
    cudaGetSymbolAddress((void**)&xlo,  g_xlo);
    cudaGetSymbolAddress((void**)&ahi,  g_ahi);
    cudaGetSymbolAddress((void**)&alo,  g_alo);
    cudaGetSymbolAddress((void**)&qwhi, g_qwhi);
    cudaGetSymbolAddress((void**)&qwlo, g_qwlo);
    cudaGetSymbolAddress((void**)&pwhi, g_pwhi);
    cudaGetSymbolAddress((void**)&pwlo, g_pwlo);

    cudaFuncSetAttribute(gemm_mma_kernel, cudaFuncAttributeMaxDynamicSharedMemorySize, GEMM_SMEM);
    cudaFuncSetAttribute(attn_kernel,     cudaFuncAttributeMaxDynamicSharedMemorySize, ATT_SMEM);

    {
        int n4 = MTOT * DIM / 4;
        split_kernel<<<(n4 + 255) / 256, 256>>>(x, xhi, xlo, n4);
        int w4 = QKVN * DIM / 4;
        split_kernel<<<(w4 + 255) / 256, 256>>>(qkv_w, qwhi, qwlo, w4);
        int p4 = DIM * DIM / 4;
        split_kernel<<<(p4 + 255) / 256, 256>>>(proj_w, pwhi, pwlo, p4);
    }

    gemm_mma_kernel<<<dim3(MTOT / BM, QKVN / BN), 256, GEMM_SMEM>>>(
        xhi, xlo, qwhi, qwlo, qkv_b, qkv_s, QKVN);

    attn_kernel<<<dim3(NWIN, NHEAD / HB), ATT_THREADS, ATT_SMEM>>>(
        qkv_s, table, ahi, alo);

    gemm_mma_kernel<<<dim3(MTOT / BM, DIM / BN), 256, GEMM_SMEM>>>(
        ahi, alo, pwhi, pwlo, proj_b, out, DIM);
}

// round 10
// speedup vs baseline: 1.1734x; 1.1734x over previous
#include <cuda_runtime.h>
#include <cuda_bf16.h>
#include <cstdint>

// ---------------- problem constants ----------------
#define NWIN   2048
#define NTOK   66
#define MTOT   (NWIN * NTOK)       // 135168
#define DIM    256
#define QKVN   768
#define NHEAD  8
#define HD     32
#define TOKNUM 2
#define GK     256

// ---------------- scratch ----------------
__device__ float          g_qkv [(size_t)MTOT * QKVN];
__device__ __nv_bfloat16  g_xhi [(size_t)MTOT * DIM];
__device__ __nv_bfloat16  g_xlo [(size_t)MTOT * DIM];
__device__ __nv_bfloat16  g_ahi [(size_t)MTOT * DIM];
__device__ __nv_bfloat16  g_alo [(size_t)MTOT * DIM];
__device__ __nv_bfloat16  g_qwhi[(size_t)QKVN * DIM];
__device__ __nv_bfloat16  g_qwlo[(size_t)QKVN * DIM];
__device__ __nv_bfloat16  g_pwhi[(size_t)DIM * DIM];
__device__ __nv_bfloat16  g_pwlo[(size_t)DIM * DIM];

// ---------------- helpers ----------------
__device__ __forceinline__ uint32_t smem_u32(const void* p) {
    uint32_t a;
    asm("{ .reg .u64 t; cvta.to.shared.u64 t, %1; cvt.u32.u64 %0, t; }"
        : "=r"(a) : "l"(p));
    return a;
}
__device__ __forceinline__ void ldsm4(uint32_t* r, uint32_t addr) {
    asm volatile("ldmatrix.sync.aligned.m8n8.x4.shared.b16 {%0,%1,%2,%3}, [%4];"
                 : "=r"(r[0]), "=r"(r[1]), "=r"(r[2]), "=r"(r[3]) : "r"(addr));
}
__device__ __forceinline__ void mma_bf16(float* c, const uint32_t* a,
                                         uint32_t b0, uint32_t b1) {
    asm volatile("mma.sync.aligned.m16n8k16.row.col.f32.bf16.bf16.f32 "
                 "{%0,%1,%2,%3}, {%4,%5,%6,%7}, {%8,%9}, {%0,%1,%2,%3};"
                 : "+f"(c[0]), "+f"(c[1]), "+f"(c[2]), "+f"(c[3])
                 : "r"(a[0]), "r"(a[1]), "r"(a[2]), "r"(a[3]),
                   "r"(b0), "r"(b1));
}
#define CP_ASYNC16(dst, src) \
    asm volatile("cp.async.cg.shared.global [%0], [%1], 16;" :: "r"(dst), "l"(src))
#define CP_COMMIT() asm volatile("cp.async.commit_group;" ::: "memory")

// ---------------- fp32 -> bf16 hi/lo split ----------------
__global__ void split_kernel(const float* __restrict__ in,
                             __nv_bfloat16* __restrict__ hi,
                             __nv_bfloat16* __restrict__ lo, int n4)
{
    int i = blockIdx.x * blockDim.x + threadIdx.x;
    if (i >= n4) return;
    float4 v = ((const float4*)in)[i];
    __nv_bfloat16 h0 = __float2bfloat16(v.x);
    __nv_bfloat16 h1 = __float2bfloat16(v.y);
    __nv_bfloat16 h2 = __float2bfloat16(v.z);
    __nv_bfloat16 h3 = __float2bfloat16(v.w);
    __nv_bfloat16 l0 = __float2bfloat16(v.x - __bfloat162float(h0));
    __nv_bfloat16 l1 = __float2bfloat16(v.y - __bfloat162float(h1));
    __nv_bfloat16 l2 = __float2bfloat16(v.z - __bfloat162float(h2));
    __nv_bfloat16 l3 = __float2bfloat16(v.w - __bfloat162float(h3));
    ((__nv_bfloat162*)hi)[2 * i + 0] = __nv_bfloat162(h0, h1);
    ((__nv_bfloat162*)hi)[2 * i + 1] = __nv_bfloat162(h2, h3);
    ((__nv_bfloat162*)lo)[2 * i + 0] = __nv_bfloat162(l0, l1);
    ((__nv_bfloat162*)lo)[2 * i + 1] = __nv_bfloat162(l2, l3);
}

// ---------------- HMMA GEMM: BK=32, swizzled 3-stage, 1 sync/chunk ---------
// CTA 128x128, 8 warps (2x4), warp tile 64x32, bf16 hi/lo 3-pass (pass-outer).
// Stage = 4 arrays x 128 rows x 64B (swizzled) = 32KB; 3 stages = 96KB -> 2 CTA/SM.
#define BM 128
#define BN 128
#define BKK 32
#define ROWB 64u                          // 32 bf16 = 64 bytes per row
#define ARR_BYTES (128u * ROWB)           // 8192
#define STAGE_BYTES (4u * ARR_BYTES)      // 32768
#define STAGES 3
#define GEMM_SMEM (STAGES * STAGE_BYTES)  // 98304
#define NCHUNK (GK / BKK)                 // 8

// swizzle: 16B chunk index ch (0..3) within a 64B row
__device__ __forceinline__ uint32_t swz(uint32_t row, uint32_t ch) {
    return row * ROWB + ((ch ^ ((row >> 1) & 3u)) << 4);
}

__global__ __launch_bounds__(256, 2)
void gemm_mma_kernel(const __nv_bfloat16* __restrict__ Ahi,
                     const __nv_bfloat16* __restrict__ Alo,
                     const __nv_bfloat16* __restrict__ Bhi,
                     const __nv_bfloat16* __restrict__ Blo,
                     const float* __restrict__ bias,
                     float* __restrict__ C, int N)
{
    extern __shared__ __nv_bfloat16 smbuf[];
    const uint32_t sbase = smem_u32(smbuf);
    const int tid  = threadIdx.x;
    const int lane = tid & 31;
    const int wid  = tid >> 5;
    const int wm   = wid >> 2;
    const int wn   = wid & 3;
    const int m0 = blockIdx.x * BM;
    const int n0 = blockIdx.y * BN;

    float acc[4][4][4];
#pragma unroll
    for (int i = 0; i < 4; i++)
#pragma unroll
        for (int j = 0; j < 4; j++)
#pragma unroll
            for (int q = 0; q < 4; q++) acc[i][j][q] = 0.0f;

    auto load_stage = [&](int c, int s) {
        const int k0 = c * BKK;
        const uint32_t stb = sbase + (uint32_t)s * STAGE_BYTES;
#pragma unroll
        for (int it = 0; it < 8; it++) {
            int t = tid + it * 256;            // 0..2047
            int arr = t >> 9;                  // 0..3
            int rem = t & 511;
            uint32_t row = (uint32_t)(rem >> 2);
            uint32_t ch  = (uint32_t)(rem & 3);
            const __nv_bfloat16* g;
            if (arr == 0)      g = Ahi + (size_t)(m0 + row) * GK + k0 + ch * 8;
            else if (arr == 1) g = Alo + (size_t)(m0 + row) * GK + k0 + ch * 8;
            else if (arr == 2) g = Bhi + (size_t)(n0 + row) * GK + k0 + ch * 8;
            else               g = Blo + (size_t)(n0 + row) * GK + k0 + ch * 8;
            uint32_t dst = stb + (uint32_t)arr * ARR_BYTES + swz(row, ch);
            CP_ASYNC16(dst, g);
        }
        CP_COMMIT();
    };

    load_stage(0, 0);
    load_stage(1, 1);

    const int a_row = (lane & 15);
    const int a_kof = (lane >> 4) << 3;            // 0 or 8 (bf16 elems)
    const int b_row = (lane & 7) + ((lane >> 4) << 3);
    const int b_kof = ((lane >> 3) & 1) << 3;

    int stage = 0;
    for (int c = 0; c < NCHUNK; c++) {
        if (c < NCHUNK - 1) asm volatile("cp.async.wait_group 1;" ::: "memory");
        else                asm volatile("cp.async.wait_group 0;" ::: "memory");
        __syncthreads();
        // single barrier/chunk: buffer (c+2)%3 was consumed in chunk c-1,
        // and the barrier above proves every warp finished those reads.
        if (c + 2 < NCHUNK) {
            int s2 = stage + 2; if (s2 >= STAGES) s2 -= STAGES;
            load_stage(c + 2, s2);
        }

        const uint32_t st = sbase + (uint32_t)stage * STAGE_BYTES;
        const uint32_t sAhi = st;
        const uint32_t sAlo = st + ARR_BYTES;
        const uint32_t sBhi = st + 2u * ARR_BYTES;
        const uint32_t sBlo = st + 3u * ARR_BYTES;

#pragma unroll
        for (int ks = 0; ks < 2; ks++) {
            uint32_t ah[4][4], al[4][4], bh[2][4], bl[2][4];
#pragma unroll
            for (int mi = 0; mi < 4; mi++) {
                uint32_t row = (uint32_t)(wm * 64 + mi * 16 + a_row);
                uint32_t ch  = (uint32_t)(ks * 16 + a_kof) >> 3;
                uint32_t off = swz(row, ch);
                ldsm4(ah[mi], sAhi + off);
                ldsm4(al[mi], sAlo + off);
            }
#pragma unroll
            for (int nt = 0; nt < 2; nt++) {
                uint32_t row = (uint32_t)(wn * 32 + nt * 16 + b_row);
                uint32_t ch  = (uint32_t)(ks * 16 + b_kof) >> 3;
                uint32_t off = swz(row, ch);
                ldsm4(bh[nt], sBhi + off);
                ldsm4(bl[nt], sBlo + off);
            }
            // pass-outer ordering: adjacent MMAs use different accumulators
#pragma unroll
            for (int mi = 0; mi < 4; mi++)
#pragma unroll
                for (int nj = 0; nj < 4; nj++)
                    mma_bf16(acc[mi][nj], ah[mi],
                             bh[nj >> 1][(nj & 1) * 2], bh[nj >> 1][(nj & 1) * 2 + 1]);
#pragma unroll
            for (int mi = 0; mi < 4; mi++)
#pragma unroll
                for (int nj = 0; nj < 4; nj++)
                    mma_bf16(acc[mi][nj], ah[mi],
                             bl[nj >> 1][(nj & 1) * 2], bl[nj >> 1][(nj & 1) * 2 + 1]);
#pragma unroll
            for (int mi = 0; mi < 4; mi++)
#pragma unroll
                for (int nj = 0; nj < 4; nj++)
                    mma_bf16(acc[mi][nj], al[mi],
                             bh[nj >> 1][(nj & 1) * 2], bh[nj >> 1][(nj & 1) * 2 + 1]);
        }
        if (++stage >= STAGES) stage = 0;
    }

#pragma unroll
    for (int mi = 0; mi < 4; mi++) {
        int row = m0 + wm * 64 + mi * 16 + (lane >> 2);
#pragma unroll
        for (int nj = 0; nj < 4; nj++) {
            int col = n0 + wn * 32 + nj * 8 + (lane & 3) * 2;
            float2 bv = *(const float2*)&bias[col];
            float2 v0 = make_float2(acc[mi][nj][0] + bv.x, acc[mi][nj][1] + bv.y);
            float2 v1 = make_float2(acc[mi][nj][2] + bv.x, acc[mi][nj][3] + bv.y);
            *(float2*)&C[(size_t)row * N + col] = v0;
            *(float2*)&C[(size_t)(row + 8) * N + col] = v1;
        }
    }
}

// ---------------- attention: 4 heads per CTA, 2 CTAs per window ------------
#define HB       4
#define ATT_THREADS 288
#define AOFF_VSM  (HB * 66 * 32)
#define AOFF_OHI  (2 * HB * 66 * 32)
#define AOFF_OLO  (AOFF_OHI + (66 * 128) / 2)
#define AOFF_TAB  (AOFF_OLO + (66 * 128) / 2)
#define ATT_SMEM  ((AOFF_TAB + 1800) * 4)

__global__ __launch_bounds__(ATT_THREADS, 2)
void attn_kernel(const float* __restrict__ qkv,
                 const float* __restrict__ table,
                 __nv_bfloat16* __restrict__ ohi,
                 __nv_bfloat16* __restrict__ olo)
{
    extern __shared__ float sm[];
    float* ksm = sm;
    float* vsm = sm + AOFF_VSM;
    __nv_bfloat16* osm_hi = (__nv_bfloat16*)(sm + AOFF_OHI);
    __nv_bfloat16* osm_lo = (__nv_bfloat16*)(sm + AOFF_OLO);
    float* tab = sm + AOFF_TAB;

    const int b = blockIdx.x;
    const int hbase = blockIdx.y * HB;
    const int tid = threadIdx.x;
    const size_t base = (size_t)b * NTOK * QKVN;

    for (int t = tid; t < NTOK * 64; t += ATT_THREADS) {
        int tok = t >> 6;
        int r = t & 63;
        int isV = r >> 5;
        int c4 = r & 31;
        float4 v = *(const float4*)&qkv[base + (size_t)tok * QKVN + 256 +
                                        isV * 256 + hbase * 32 + c4 * 4];
        int lh = c4 >> 3, d = (c4 & 7) * 4;
        float* dstp = isV ? vsm : ksm;
        *(float4*)&dstp[(lh * NTOK + tok) * 32 + d] = v;
    }
    for (int t = tid; t < 1800; t += ATT_THREADS) tab[t] = table[t];
    __syncthreads();

    if (tid < HB * NTOK) {
        const int lh = tid / NTOK;
        const int i = tid - lh * NTOK;
        const int h = hbase + lh;
        const float scale = 0.1767766952966369f;

        float qr[32];
#pragma unroll
        for (int d4 = 0; d4 < 8; d4++) {
            float4 qv = *(const float4*)&qkv[base + (size_t)i * QKVN + h * 32 + d4 * 4];
            qr[d4 * 4 + 0] = qv.x * scale; qr[d4 * 4 + 1] = qv.y * scale;
            qr[d4 * 4 + 2] = qv.z * scale; qr[d4 * 4 + 3] = qv.w * scale;
        }

        const float* krow = &ksm[lh * NTOK * 32];
        const float* vrow = &vsm[lh * NTOK * 32];
        const bool addbias = (i >= TOKNUM);
        const int qi = addbias ? (i - TOKNUM) : 0;
        const int yi = qi >> 3, xi = qi & 7;

        auto score = [&](int j) -> float {
            float a0 = 0.f, a1 = 0.f, a2 = 0.f, a3 = 0.f;
            const float* kp = &krow[j * 32];
#pragma unroll
            for (int d4 = 0; d4 < 8; d4++) {
                float4 kv = *(const float4*)&kp[d4 * 4];
                a0 = fmaf(qr[d4 * 4 + 0], kv.x, a0);
                a1 = fmaf(qr[d4 * 4 + 1], kv.y, a1);
                a2 = fmaf(qr[d4 * 4 + 2], kv.z, a2);
                a3 = fmaf(qr[d4 * 4 + 3], kv.w, a3);
            }
            return (a0 + a1) + (a2 + a3);
        };

        float4 oacc[8];
        float s0 = score(0);
        float s1 = score(1);
        float m = fmaxf(s0, s1);
        float p0 = __expf(s0 - m);
        float p1 = __expf(s1 - m);
        float l = p0 + p1;
        {
            const float* v0 = &vrow[0];
            const float* v1 = &vrow[32];
#pragma unroll
            for (int d4 = 0; d4 < 8; d4++) {
                float4 va = *(const float4*)&v0[d4 * 4];
                float4 vb = *(const float4*)&v1[d4 * 4];
                oacc[d4].x = p0 * va.x + p1 * vb.x;
                oacc[d4].y = p0 * va.y + p1 * vb.y;
                oacc[d4].z = p0 * va.z + p1 * vb.z;
                oacc[d4].w = p0 * va.w + p1 * vb.w;
            }
        }

        for (int jb = 0; jb < 8; jb++) {
            const float* trow = &tab[(((yi - jb + 7) * 15) + xi + 7) * NHEAD + h];
            float sc[8];
            float bm = -1e30f;
#pragma unroll
            for (int jj = 0; jj < 8; jj++) {
                float s = score(jb * 8 + jj + TOKNUM);
                if (addbias) s += trow[-jj * NHEAD];
                sc[jj] = s;
                bm = fmaxf(bm, s);
            }
            float m_new = fmaxf(m, bm);
            float f = __expf(m - m_new);
            m = m_new;
            l *= f;
#pragma unroll
            for (int d4 = 0; d4 < 8; d4++) {
                oacc[d4].x *= f; oacc[d4].y *= f;
                oacc[d4].z *= f; oacc[d4].w *= f;
            }
#pragma unroll
            for (int jj = 0; jj < 8; jj++) {
                float p = __expf(sc[jj] - m);
                l += p;
                const float* vp = &vrow[(jb * 8 + jj + TOKNUM) * 32];
#pragma unroll
                for (int d4 = 0; d4 < 8; d4++) {
                    float4 vv = *(const float4*)&vp[d4 * 4];
                    oacc[d4].x = fmaf(p, vv.x, oacc[d4].x);
                    oacc[d4].y = fmaf(p, vv.y, oacc[d4].y);
                    oacc[d4].z = fmaf(p, vv.z, oacc[d4].z);
                    oacc[d4].w = fmaf(p, vv.w, oacc[d4].w);
                }
            }
        }

        const float inv = 1.0f / l;
        __nv_bfloat16* ph = &osm_hi[i * 128 + lh * 32];
        __nv_bfloat16* pl = &osm_lo[i * 128 + lh * 32];
#pragma unroll
        for (int d4 = 0; d4 < 8; d4++) {
            float o[4] = {oacc[d4].x * inv, oacc[d4].y * inv,
                          oacc[d4].z * inv, oacc[d4].w * inv};
#pragma unroll
            for (int q = 0; q < 4; q++) {
                __nv_bfloat16 hh = __float2bfloat16(o[q]);
                ph[d4 * 4 + q] = hh;
                pl[d4 * 4 + q] = __float2bfloat16(o[q] - __bfloat162float(hh));
            }
        }
    }
    __syncthreads();

    uint4* gh = (uint4*)(ohi + (size_t)b * NTOK * DIM + hbase * 32);
    uint4* gl = (uint4*)(olo + (size_t)b * NTOK * DIM + hbase * 32);
    const uint4* shh = (const uint4*)osm_hi;
    const uint4* sll = (const uint4*)osm_lo;
    for (int t = tid; t < NTOK * 16; t += ATT_THREADS) {
        int row = t >> 4;
        int c = t & 15;
        gh[row * 32 + c] = shh[t];
        gl[row * 32 + c] = sll[t];
    }
}

// ---------------------------------------------------------------------------
extern "C" void kernel_launch(void* const* d_in, const int* in_sizes, int n_in,
                              void* d_out, int out_size)
{
    const float* x      = (const float*)d_in[0];
    const float* qkv_w  = (const float*)d_in[1];
    const float* qkv_b  = (const float*)d_in[2];
    const float* table  = (const float*)d_in[3];
    const float* proj_w = (const float*)d_in[4];
    const float* proj_b = (const float*)d_in[5];
    float* out = (float*)d_out;

    __nv_bfloat16 *xhi, *xlo, *ahi, *alo, *qwhi, *qwlo, *pwhi, *pwlo;
    float* qkv_s;
    cudaGetSymbolAddress((void**)&qkv_s, g_qkv);
    cudaGetSymbolAddress((void**)&xhi,  g_xhi);
    cudaGetSymbolAddress((void**)&xlo,  g_xlo);
    cudaGetSymbolAddress((void**)&ahi,  g_ahi);
    cudaGetSymbolAddress((void**)&alo,  g_alo);
    cudaGetSymbolAddress((void**)&qwhi, g_qwhi);
    cudaGetSymbolAddress((void**)&qwlo, g_qwlo);
    cudaGetSymbolAddress((void**)&pwhi, g_pwhi);
    cudaGetSymbolAddress((void**)&pwlo, g_pwlo);

    cudaFuncSetAttribute(gemm_mma_kernel, cudaFuncAttributeMaxDynamicSharedMemorySize, GEMM_SMEM);
    cudaFuncSetAttribute(attn_kernel,     cudaFuncAttributeMaxDynamicSharedMemorySize, ATT_SMEM);

    {
        int n4 = MTOT * DIM / 4;
        split_kernel<<<(n4 + 255) / 256, 256>>>(x, xhi, xlo, n4);
        int w4 = QKVN * DIM / 4;
        split_kernel<<<(w4 + 255) / 256, 256>>>(qkv_w, qwhi, qwlo, w4);
        int p4 = DIM * DIM / 4;
        split_kernel<<<(p4 + 255) / 256, 256>>>(proj_w, pwhi, pwlo, p4);
    }

    gemm_mma_kernel<<<dim3(MTOT / BM, QKVN / BN), 256, GEMM_SMEM>>>(
        xhi, xlo, qwhi, qwlo, qkv_b, qkv_s, QKVN);

    attn_kernel<<<dim3(NWIN, NHEAD / HB), ATT_THREADS, ATT_SMEM>>>(
        qkv_s, table, ahi, alo);

    gemm_mma_kernel<<<dim3(MTOT / BM, DIM / BN), 256, GEMM_SMEM>>>(
        ahi, alo, pwhi, pwlo, proj_b, out, DIM);
}

// round 11
// speedup vs baseline: 1.2505x; 1.0656x over previous
#include <cuda_runtime.h>
#include <cuda_bf16.h>
#include <cstdint>

// ---------------- problem constants ----------------
#define NWIN   2048
#define NTOK   66
#define MTOT   (NWIN * NTOK)       // 135168
#define DIM    256
#define QKVN   768
#define NHEAD  8
#define HD     32
#define TOKNUM 2
#define GK     256

// ---------------- scratch ----------------
__device__ float          g_qkv [(size_t)MTOT * QKVN];
__device__ __nv_bfloat16  g_xhi [(size_t)MTOT * DIM];
__device__ __nv_bfloat16  g_xlo [(size_t)MTOT * DIM];
__device__ __nv_bfloat16  g_ahi [(size_t)MTOT * DIM];
__device__ __nv_bfloat16  g_alo [(size_t)MTOT * DIM];
__device__ __nv_bfloat16  g_qwhi[(size_t)QKVN * DIM];
__device__ __nv_bfloat16  g_qwlo[(size_t)QKVN * DIM];
__device__ __nv_bfloat16  g_pwhi[(size_t)DIM * DIM];
__device__ __nv_bfloat16  g_pwlo[(size_t)DIM * DIM];

// ---------------- helpers ----------------
__device__ __forceinline__ uint32_t smem_u32(const void* p) {
    uint32_t a;
    asm("{ .reg .u64 t; cvta.to.shared.u64 t, %1; cvt.u32.u64 %0, t; }"
        : "=r"(a) : "l"(p));
    return a;
}
__device__ __forceinline__ void ldsm4(uint32_t* r, uint32_t addr) {
    asm volatile("ldmatrix.sync.aligned.m8n8.x4.shared.b16 {%0,%1,%2,%3}, [%4];"
                 : "=r"(r[0]), "=r"(r[1]), "=r"(r[2]), "=r"(r[3]) : "r"(addr));
}
__device__ __forceinline__ void mma_bf16(float* c, const uint32_t* a,
                                         uint32_t b0, uint32_t b1) {
    asm volatile("mma.sync.aligned.m16n8k16.row.col.f32.bf16.bf16.f32 "
                 "{%0,%1,%2,%3}, {%4,%5,%6,%7}, {%8,%9}, {%0,%1,%2,%3};"
                 : "+f"(c[0]), "+f"(c[1]), "+f"(c[2]), "+f"(c[3])
                 : "r"(a[0]), "r"(a[1]), "r"(a[2]), "r"(a[3]),
                   "r"(b0), "r"(b1));
}
#define CP_ASYNC16(dst, src) \
    asm volatile("cp.async.cg.shared.global [%0], [%1], 16;" :: "r"(dst), "l"(src))
#define CP_COMMIT() asm volatile("cp.async.commit_group;" ::: "memory")

// ---------------- fp32 -> bf16 hi/lo split ----------------
__global__ void split_kernel(const float* __restrict__ in,
                             __nv_bfloat16* __restrict__ hi,
                             __nv_bfloat16* __restrict__ lo, int n4)
{
    int i = blockIdx.x * blockDim.x + threadIdx.x;
    if (i >= n4) return;
    float4 v = ((const float4*)in)[i];
    __nv_bfloat16 h0 = __float2bfloat16(v.x);
    __nv_bfloat16 h1 = __float2bfloat16(v.y);
    __nv_bfloat16 h2 = __float2bfloat16(v.z);
    __nv_bfloat16 h3 = __float2bfloat16(v.w);
    __nv_bfloat16 l0 = __float2bfloat16(v.x - __bfloat162float(h0));
    __nv_bfloat16 l1 = __float2bfloat16(v.y - __bfloat162float(h1));
    __nv_bfloat16 l2 = __float2bfloat16(v.z - __bfloat162float(h2));
    __nv_bfloat16 l3 = __float2bfloat16(v.w - __bfloat162float(h3));
    ((__nv_bfloat162*)hi)[2 * i + 0] = __nv_bfloat162(h0, h1);
    ((__nv_bfloat162*)hi)[2 * i + 1] = __nv_bfloat162(h2, h3);
    ((__nv_bfloat162*)lo)[2 * i + 0] = __nv_bfloat162(l0, l1);
    ((__nv_bfloat162*)lo)[2 * i + 1] = __nv_bfloat162(l2, l3);
}

// ---------------- HMMA GEMM: BK=32, swizzled 3-stage, 1 sync/chunk ---------
#define BM 128
#define BN 128
#define BKK 32
#define ROWB 64u
#define ARR_BYTES (128u * ROWB)
#define STAGE_BYTES (4u * ARR_BYTES)
#define STAGES 3
#define GEMM_SMEM (STAGES * STAGE_BYTES)  // 98304
#define NCHUNK (GK / BKK)                 // 8

__device__ __forceinline__ uint32_t swz(uint32_t row, uint32_t ch) {
    return row * ROWB + ((ch ^ ((row >> 1) & 3u)) << 4);
}

__global__ __launch_bounds__(256, 2)
void gemm_mma_kernel(const __nv_bfloat16* __restrict__ Ahi,
                     const __nv_bfloat16* __restrict__ Alo,
                     const __nv_bfloat16* __restrict__ Bhi,
                     const __nv_bfloat16* __restrict__ Blo,
                     const float* __restrict__ bias,
                     float* __restrict__ C, int N)
{
    extern __shared__ __nv_bfloat16 smbuf[];
    const uint32_t sbase = smem_u32(smbuf);
    const int tid  = threadIdx.x;
    const int lane = tid & 31;
    const int wid  = tid >> 5;
    const int wm   = wid >> 2;
    const int wn   = wid & 3;
    const int m0 = blockIdx.x * BM;
    const int n0 = blockIdx.y * BN;

    float acc[4][4][4];
#pragma unroll
    for (int i = 0; i < 4; i++)
#pragma unroll
        for (int j = 0; j < 4; j++)
#pragma unroll
            for (int q = 0; q < 4; q++) acc[i][j][q] = 0.0f;

    auto load_stage = [&](int c, int s) {
        const int k0 = c * BKK;
        const uint32_t stb = sbase + (uint32_t)s * STAGE_BYTES;
#pragma unroll
        for (int it = 0; it < 8; it++) {
            int t = tid + it * 256;
            int arr = t >> 9;
            int rem = t & 511;
            uint32_t row = (uint32_t)(rem >> 2);
            uint32_t ch  = (uint32_t)(rem & 3);
            const __nv_bfloat16* g;
            if (arr == 0)      g = Ahi + (size_t)(m0 + row) * GK + k0 + ch * 8;
            else if (arr == 1) g = Alo + (size_t)(m0 + row) * GK + k0 + ch * 8;
            else if (arr == 2) g = Bhi + (size_t)(n0 + row) * GK + k0 + ch * 8;
            else               g = Blo + (size_t)(n0 + row) * GK + k0 + ch * 8;
            uint32_t dst = stb + (uint32_t)arr * ARR_BYTES + swz(row, ch);
            CP_ASYNC16(dst, g);
        }
        CP_COMMIT();
    };

    load_stage(0, 0);
    load_stage(1, 1);

    const int a_row = (lane & 15);
    const int a_kof = (lane >> 4) << 3;
    const int b_row = (lane & 7) + ((lane >> 4) << 3);
    const int b_kof = ((lane >> 3) & 1) << 3;

    int stage = 0;
    for (int c = 0; c < NCHUNK; c++) {
        if (c < NCHUNK - 1) asm volatile("cp.async.wait_group 1;" ::: "memory");
        else                asm volatile("cp.async.wait_group 0;" ::: "memory");
        __syncthreads();
        if (c + 2 < NCHUNK) {
            int s2 = stage + 2; if (s2 >= STAGES) s2 -= STAGES;
            load_stage(c + 2, s2);
        }

        const uint32_t st = sbase + (uint32_t)stage * STAGE_BYTES;
        const uint32_t sAhi = st;
        const uint32_t sAlo = st + ARR_BYTES;
        const uint32_t sBhi = st + 2u * ARR_BYTES;
        const uint32_t sBlo = st + 3u * ARR_BYTES;

#pragma unroll
        for (int ks = 0; ks < 2; ks++) {
            uint32_t ah[4][4], al[4][4], bh[2][4], bl[2][4];
#pragma unroll
            for (int mi = 0; mi < 4; mi++) {
                uint32_t row = (uint32_t)(wm * 64 + mi * 16 + a_row);
                uint32_t ch  = (uint32_t)(ks * 16 + a_kof) >> 3;
                uint32_t off = swz(row, ch);
                ldsm4(ah[mi], sAhi + off);
                ldsm4(al[mi], sAlo + off);
            }
#pragma unroll
            for (int nt = 0; nt < 2; nt++) {
                uint32_t row = (uint32_t)(wn * 32 + nt * 16 + b_row);
                uint32_t ch  = (uint32_t)(ks * 16 + b_kof) >> 3;
                uint32_t off = swz(row, ch);
                ldsm4(bh[nt], sBhi + off);
                ldsm4(bl[nt], sBlo + off);
            }
#pragma unroll
            for (int mi = 0; mi < 4; mi++)
#pragma unroll
                for (int nj = 0; nj < 4; nj++)
                    mma_bf16(acc[mi][nj], ah[mi],
                             bh[nj >> 1][(nj & 1) * 2], bh[nj >> 1][(nj & 1) * 2 + 1]);
#pragma unroll
            for (int mi = 0; mi < 4; mi++)
#pragma unroll
                for (int nj = 0; nj < 4; nj++)
                    mma_bf16(acc[mi][nj], ah[mi],
                             bl[nj >> 1][(nj & 1) * 2], bl[nj >> 1][(nj & 1) * 2 + 1]);
#pragma unroll
            for (int mi = 0; mi < 4; mi++)
#pragma unroll
                for (int nj = 0; nj < 4; nj++)
                    mma_bf16(acc[mi][nj], al[mi],
                             bh[nj >> 1][(nj & 1) * 2], bh[nj >> 1][(nj & 1) * 2 + 1]);
        }
        if (++stage >= STAGES) stage = 0;
    }

#pragma unroll
    for (int mi = 0; mi < 4; mi++) {
        int row = m0 + wm * 64 + mi * 16 + (lane >> 2);
#pragma unroll
        for (int nj = 0; nj < 4; nj++) {
            int col = n0 + wn * 32 + nj * 8 + (lane & 3) * 2;
            float2 bv = *(const float2*)&bias[col];
            float2 v0 = make_float2(acc[mi][nj][0] + bv.x, acc[mi][nj][1] + bv.y);
            float2 v1 = make_float2(acc[mi][nj][2] + bv.x, acc[mi][nj][3] + bv.y);
            *(float2*)&C[(size_t)row * N + col] = v0;
            *(float2*)&C[(size_t)(row + 8) * N + col] = v1;
        }
    }
}

// ---------------- attention: 2 queries/thread, 4 heads/CTA -----------------
// worker w (0..131): head lh = w/33, base query iq = w%33 -> queries iq, iq+33
#define HB       4
#define ATT_THREADS 160
#define AOFF_VSM  (HB * 66 * 32)
#define AOFF_OHI  (2 * HB * 66 * 32)
#define AOFF_OLO  (AOFF_OHI + (66 * 128) / 2)
#define AOFF_TAB  (AOFF_OLO + (66 * 128) / 2)
#define ATT_SMEM  ((AOFF_TAB + 1800) * 4)

__global__ __launch_bounds__(ATT_THREADS, 2)
void attn_kernel(const float* __restrict__ qkv,
                 const float* __restrict__ table,
                 __nv_bfloat16* __restrict__ ohi,
                 __nv_bfloat16* __restrict__ olo)
{
    extern __shared__ float sm[];
    float* ksm = sm;
    float* vsm = sm + AOFF_VSM;
    __nv_bfloat16* osm_hi = (__nv_bfloat16*)(sm + AOFF_OHI);
    __nv_bfloat16* osm_lo = (__nv_bfloat16*)(sm + AOFF_OLO);
    float* tab = sm + AOFF_TAB;

    const int b = blockIdx.x;
    const int hbase = blockIdx.y * HB;
    const int tid = threadIdx.x;
    const size_t base = (size_t)b * NTOK * QKVN;

    for (int t = tid; t < NTOK * 64; t += ATT_THREADS) {
        int tok = t >> 6;
        int r = t & 63;
        int isV = r >> 5;
        int c4 = r & 31;
        float4 v = *(const float4*)&qkv[base + (size_t)tok * QKVN + 256 +
                                        isV * 256 + hbase * 32 + c4 * 4];
        int lh = c4 >> 3, d = (c4 & 7) * 4;
        float* dstp = isV ? vsm : ksm;
        *(float4*)&dstp[(lh * NTOK + tok) * 32 + d] = v;
    }
    for (int t = tid; t < 1800; t += ATT_THREADS) tab[t] = table[t];
    __syncthreads();

    if (tid < HB * 33) {
        const int lh = tid / 33;
        const int iq = tid - lh * 33;
        const int h = hbase + lh;
        const float scale = 0.1767766952966369f;
        const int qi0 = iq;            // query 0: token iq
        const int qi1 = iq + 33;       // query 1: token iq+33

        float qr[2][32];
#pragma unroll
        for (int d4 = 0; d4 < 8; d4++) {
            float4 qa = *(const float4*)&qkv[base + (size_t)qi0 * QKVN + h * 32 + d4 * 4];
            float4 qb = *(const float4*)&qkv[base + (size_t)qi1 * QKVN + h * 32 + d4 * 4];
            qr[0][d4 * 4 + 0] = qa.x * scale; qr[0][d4 * 4 + 1] = qa.y * scale;
            qr[0][d4 * 4 + 2] = qa.z * scale; qr[0][d4 * 4 + 3] = qa.w * scale;
            qr[1][d4 * 4 + 0] = qb.x * scale; qr[1][d4 * 4 + 1] = qb.y * scale;
            qr[1][d4 * 4 + 2] = qb.z * scale; qr[1][d4 * 4 + 3] = qb.w * scale;
        }

        const float* krow = &ksm[lh * NTOK * 32];
        const float* vrow = &vsm[lh * NTOK * 32];
        const bool ab0 = (qi0 >= TOKNUM);         // q1 always >= 2
        const int s0i = ab0 ? (qi0 - TOKNUM) : 0;
        const int s1i = qi1 - TOKNUM;
        const int yi0 = s0i >> 3, xi0 = s0i & 7;
        const int yi1 = s1i >> 3, xi1 = s1i & 7;

        // shared-load dual score for key j
        auto score2 = [&](int j, float& r0, float& r1) {
            float a00 = 0.f, a01 = 0.f, a10 = 0.f, a11 = 0.f;
            const float* kp = &krow[j * 32];
#pragma unroll
            for (int d4 = 0; d4 < 8; d4++) {
                float4 kv = *(const float4*)&kp[d4 * 4];
                a00 = fmaf(qr[0][d4 * 4 + 0], kv.x, a00);
                a01 = fmaf(qr[0][d4 * 4 + 1], kv.y, a01);
                a00 = fmaf(qr[0][d4 * 4 + 2], kv.z, a00);
                a01 = fmaf(qr[0][d4 * 4 + 3], kv.w, a01);
                a10 = fmaf(qr[1][d4 * 4 + 0], kv.x, a10);
                a11 = fmaf(qr[1][d4 * 4 + 1], kv.y, a11);
                a10 = fmaf(qr[1][d4 * 4 + 2], kv.z, a10);
                a11 = fmaf(qr[1][d4 * 4 + 3], kv.w, a11);
            }
            r0 = a00 + a01;
            r1 = a10 + a11;
        };

        float4 oacc[2][8];
        float m[2], l[2];
        // seed: tokens 0 and 1 (never biased)
        {
            float s00, s01, s10, s11;
            score2(0, s00, s10);
            score2(1, s01, s11);
            m[0] = fmaxf(s00, s01);
            m[1] = fmaxf(s10, s11);
            float p00 = __expf(s00 - m[0]), p01 = __expf(s01 - m[0]);
            float p10 = __expf(s10 - m[1]), p11 = __expf(s11 - m[1]);
            l[0] = p00 + p01;
            l[1] = p10 + p11;
            const float* v0 = &vrow[0];
            const float* v1 = &vrow[32];
#pragma unroll
            for (int d4 = 0; d4 < 8; d4++) {
                float4 va = *(const float4*)&v0[d4 * 4];
                float4 vb = *(const float4*)&v1[d4 * 4];
                oacc[0][d4].x = p00 * va.x + p01 * vb.x;
                oacc[0][d4].y = p00 * va.y + p01 * vb.y;
                oacc[0][d4].z = p00 * va.z + p01 * vb.z;
                oacc[0][d4].w = p00 * va.w + p01 * vb.w;
                oacc[1][d4].x = p10 * va.x + p11 * vb.x;
                oacc[1][d4].y = p10 * va.y + p11 * vb.y;
                oacc[1][d4].z = p10 * va.z + p11 * vb.z;
                oacc[1][d4].w = p10 * va.w + p11 * vb.w;
            }
        }

        for (int jb = 0; jb < 8; jb++) {
            const float* trow0 = &tab[(((yi0 - jb + 7) * 15) + xi0 + 7) * NHEAD + h];
            const float* trow1 = &tab[(((yi1 - jb + 7) * 15) + xi1 + 7) * NHEAD + h];
            float sc[2][8];
            float bm0 = -1e30f, bm1 = -1e30f;
#pragma unroll
            for (int jj = 0; jj < 8; jj++) {
                float r0, r1;
                score2(jb * 8 + jj + TOKNUM, r0, r1);
                if (ab0) r0 += trow0[-jj * NHEAD];
                r1 += trow1[-jj * NHEAD];
                sc[0][jj] = r0; sc[1][jj] = r1;
                bm0 = fmaxf(bm0, r0); bm1 = fmaxf(bm1, r1);
            }
            float mn0 = fmaxf(m[0], bm0);
            float mn1 = fmaxf(m[1], bm1);
            float f0 = __expf(m[0] - mn0);
            float f1 = __expf(m[1] - mn1);
            m[0] = mn0; m[1] = mn1;
            l[0] *= f0; l[1] *= f1;
#pragma unroll
            for (int d4 = 0; d4 < 8; d4++) {
                oacc[0][d4].x *= f0; oacc[0][d4].y *= f0;
                oacc[0][d4].z *= f0; oacc[0][d4].w *= f0;
                oacc[1][d4].x *= f1; oacc[1][d4].y *= f1;
                oacc[1][d4].z *= f1; oacc[1][d4].w *= f1;
            }
#pragma unroll
            for (int jj = 0; jj < 8; jj++) {
                float p0 = __expf(sc[0][jj] - m[0]);
                float p1 = __expf(sc[1][jj] - m[1]);
                l[0] += p0; l[1] += p1;
                const float* vp = &vrow[(jb * 8 + jj + TOKNUM) * 32];
#pragma unroll
                for (int d4 = 0; d4 < 8; d4++) {
                    float4 vv = *(const float4*)&vp[d4 * 4];
                    oacc[0][d4].x = fmaf(p0, vv.x, oacc[0][d4].x);
                    oacc[0][d4].y = fmaf(p0, vv.y, oacc[0][d4].y);
                    oacc[0][d4].z = fmaf(p0, vv.z, oacc[0][d4].z);
                    oacc[0][d4].w = fmaf(p0, vv.w, oacc[0][d4].w);
                    oacc[1][d4].x = fmaf(p1, vv.x, oacc[1][d4].x);
                    oacc[1][d4].y = fmaf(p1, vv.y, oacc[1][d4].y);
                    oacc[1][d4].z = fmaf(p1, vv.z, oacc[1][d4].z);
                    oacc[1][d4].w = fmaf(p1, vv.w, oacc[1][d4].w);
                }
            }
        }

#pragma unroll
        for (int q = 0; q < 2; q++) {
            const float inv = 1.0f / l[q];
            const int tokq = q == 0 ? qi0 : qi1;
            __nv_bfloat16* ph = &osm_hi[tokq * 128 + lh * 32];
            __nv_bfloat16* pl = &osm_lo[tokq * 128 + lh * 32];
#pragma unroll
            for (int d4 = 0; d4 < 8; d4++) {
                float o[4] = {oacc[q][d4].x * inv, oacc[q][d4].y * inv,
                              oacc[q][d4].z * inv, oacc[q][d4].w * inv};
#pragma unroll
                for (int e = 0; e < 4; e++) {
                    __nv_bfloat16 hh = __float2bfloat16(o[e]);
                    ph[d4 * 4 + e] = hh;
                    pl[d4 * 4 + e] = __float2bfloat16(o[e] - __bfloat162float(hh));
                }
            }
        }
    }
    __syncthreads();

    uint4* gh = (uint4*)(ohi + (size_t)b * NTOK * DIM + hbase * 32);
    uint4* gl = (uint4*)(olo + (size_t)b * NTOK * DIM + hbase * 32);
    const uint4* shh = (const uint4*)osm_hi;
    const uint4* sll = (const uint4*)osm_lo;
    for (int t = tid; t < NTOK * 16; t += ATT_THREADS) {
        int row = t >> 4;
        int c = t & 15;
        gh[row * 32 + c] = shh[t];
        gl[row * 32 + c] = sll[t];
    }
}

// ---------------------------------------------------------------------------
extern "C" void kernel_launch(void* const* d_in, const int* in_sizes, int n_in,
                              void* d_out, int out_size)
{
    const float* x      = (const float*)d_in[0];
    const float* qkv_w  = (const float*)d_in[1];
    const float* qkv_b  = (const float*)d_in[2];
    const float* table  = (const float*)d_in[3];
    const float* proj_w = (const float*)d_in[4];
    const float* proj_b = (const float*)d_in[5];
    float* out = (float*)d_out;

    __nv_bfloat16 *xhi, *xlo, *ahi, *alo, *qwhi, *qwlo, *pwhi, *pwlo;
    float* qkv_s;
    cudaGetSymbolAddress((void**)&qkv_s, g_qkv);
    cudaGetSymbolAddress((void**)&xhi,  g_xhi);
    cudaGetSymbolAddress((void**)&xlo,  g_xlo);
    cudaGetSymbolAddress((void**)&ahi,  g_ahi);
    cudaGetSymbolAddress((void**)&alo,  g_alo);
    cudaGetSymbolAddress((void**)&qwhi, g_qwhi);
    cudaGetSymbolAddress((void**)&qwlo, g_qwlo);
    cudaGetSymbolAddress((void**)&pwhi, g_pwhi);
    cudaGetSymbolAddress((void**)&pwlo, g_pwlo);

    cudaFuncSetAttribute(gemm_mma_kernel, cudaFuncAttributeMaxDynamicSharedMemorySize, GEMM_SMEM);
    cudaFuncSetAttribute(attn_kernel,     cudaFuncAttributeMaxDynamicSharedMemorySize, ATT_SMEM);

    {
        int n4 = MTOT * DIM / 4;
        split_kernel<<<(n4 + 255) / 256, 256>>>(x, xhi, xlo, n4);
        int w4 = QKVN * DIM / 4;
        split_kernel<<<(w4 + 255) / 256, 256>>>(qkv_w, qwhi, qwlo, w4);
        int p4 = DIM * DIM / 4;
        split_kernel<<<(p4 + 255) / 256, 256>>>(proj_w, pwhi, pwlo, p4);
    }

    gemm_mma_kernel<<<dim3(MTOT / BM, QKVN / BN), 256, GEMM_SMEM>>>(
        xhi, xlo, qwhi, qwlo, qkv_b, qkv_s, QKVN);

    attn_kernel<<<dim3(NWIN, NHEAD / HB), ATT_THREADS, ATT_SMEM>>>(
        qkv_s, table, ahi, alo);

    gemm_mma_kernel<<<dim3(MTOT / BM, DIM / BN), 256, GEMM_SMEM>>>(
        ahi, alo, pwhi, pwlo, proj_b, out, DIM);
}